// round 8
// baseline (speedup 1.0000x reference)
#include <cuda_runtime.h>

// ---------------------------------------------------------------------------
// metamorphoses shooting, L=10, 96^3, B=1
// Output layout (floats), tuple order of reference():
//   [0)                image            (96^3)
//   [NV)               fields  10 x 3NV  (v_p: [q1][q2][q3][c])
//   [NV+30NV)          grads   10 x 3NV  ([c][z][y][x])
//   [NV+60NV)          residuals 11 x NV
//   [NV+60NV+11NV)     residuals_deformed (NV)
// ---------------------------------------------------------------------------

constexpr int DV  = 96;
constexpr int SLB = DV * DV;        // 9216
constexpr int NV  = DV * DV * DV;   // 884736
constexpr int NV3 = 3 * NV;
constexpr int LSTEPS = 10;

// scratch (module-static device memory: allowed per pitfalls.md)
__device__ float d_GK[19];
__device__ float g_bufA[NV3];
__device__ float g_bufB[NV3];
__device__ float g_bufC[NV3];
__device__ float g_phi[2][NV3];
__device__ float g_rd[2][NV];

// ---------------------------------------------------------------------------
// Bit-exact replicas of the reference's coordinate arithmetic.
__device__ __forceinline__ float lin95(int q) {
    const float DELTA = 2.0f / 95.0f;          // RN(2/95), matches jnp.linspace step
    return __fadd_rn(-1.0f, __fmul_rn((float)q, DELTA));
}
// deformation coord: d = lin(q) - v/10 ; px = ((d+1)*0.5)*95
__device__ __forceinline__ float def_coord(int q, float v) {
    float d = __fsub_rn(lin95(q), __fdiv_rn(v, 10.0f));
    return __fmul_rn(__fmul_rn(__fadd_rn(d, 1.0f), 0.5f), 95.0f);
}
// phi-based coord: px = ((phi+1)*0.5)*95
__device__ __forceinline__ float phi_coord(float g) {
    return __fmul_rn(__fmul_rn(__fadd_rn(g, 1.0f), 0.5f), 95.0f);
}

// index setup matching reference semantics (fx from unclamped floor)
__device__ __forceinline__ void tri_idx(float px, float py, float pz,
                                        int* ii, float* fx, float* fy, float* fz) {
    float xf = floorf(px), yf = floorf(py), zf = floorf(pz);
    *fx = __fsub_rn(px, xf); *fy = __fsub_rn(py, yf); *fz = __fsub_rn(pz, zf);
    int x0 = (int)xf; x0 = x0 < 0 ? 0 : (x0 > 95 ? 95 : x0); int x1 = x0 < 95 ? x0 + 1 : 95;
    int y0 = (int)yf; y0 = y0 < 0 ? 0 : (y0 > 95 ? 95 : y0); int y1 = y0 < 95 ? y0 + 1 : 95;
    int z0 = (int)zf; z0 = z0 < 0 ? 0 : (z0 > 95 ? 95 : z0); int z1 = z0 < 95 ? z0 + 1 : 95;
    int b00 = (z0 * DV + y0) * DV, b01 = (z0 * DV + y1) * DV;
    int b10 = (z1 * DV + y0) * DV, b11 = (z1 * DV + y1) * DV;
    ii[0] = b00 + x0; ii[1] = b00 + x1; ii[2] = b01 + x0; ii[3] = b01 + x1;
    ii[4] = b10 + x0; ii[5] = b10 + x1; ii[6] = b11 + x0; ii[7] = b11 + x1;
}

// exact replica of reference's nested lerp:
// lo = (c000*(1-fx)+c001*fx)*(1-fy) + (c010*(1-fx)+c011*fx)*fy ; same for hi;
// out = lo*(1-fz) + hi*fz
__device__ __forceinline__ float tri_lerp(const float* __restrict__ p, const int* ii,
                                          float fx, float fy, float fz) {
    float gx = __fsub_rn(1.0f, fx), gy = __fsub_rn(1.0f, fy), gz = __fsub_rn(1.0f, fz);
    float c000 = __ldg(p + ii[0]), c001 = __ldg(p + ii[1]);
    float c010 = __ldg(p + ii[2]), c011 = __ldg(p + ii[3]);
    float c100 = __ldg(p + ii[4]), c101 = __ldg(p + ii[5]);
    float c110 = __ldg(p + ii[6]), c111 = __ldg(p + ii[7]);
    float a0 = __fadd_rn(__fmul_rn(c000, gx), __fmul_rn(c001, fx));
    float a1 = __fadd_rn(__fmul_rn(c010, gx), __fmul_rn(c011, fx));
    float lo = __fadd_rn(__fmul_rn(a0, gy), __fmul_rn(a1, fy));
    float b0 = __fadd_rn(__fmul_rn(c100, gx), __fmul_rn(c101, fx));
    float b1 = __fadd_rn(__fmul_rn(c110, gx), __fmul_rn(c111, fx));
    float hi = __fadd_rn(__fmul_rn(b0, gy), __fmul_rn(b1, fy));
    return __fadd_rn(__fmul_rn(lo, gz), __fmul_rn(hi, fz));
}

// ---------------------------------------------------------------------------
__global__ void k_init_gk() {
    if (threadIdx.x == 0 && blockIdx.x == 0) {
        float v[19]; float s = 0.f;
        for (int i = 0; i < 19; i++) {
            float x = (float)(i - 9) / 3.0f;
            v[i] = expf(-0.5f * x * x);
            s += v[i];
        }
        for (int i = 0; i < 19; i++) d_GK[i] = __fdiv_rn(v[i], s);
    }
}

__global__ void __launch_bounds__(256) k_init_state() {
    int idx = blockIdx.x * 256 + threadIdx.x;
    if (idx >= NV) return;
    int q3 = idx % DV, q2 = (idx / DV) % DV, q1 = idx / SLB;
    g_rd[0][idx] = 0.f;
    // Phi[c][q1][q2][q3] = phi[q3][q2][q1][c]; identity: (lin(q1), lin(q2), lin(q3))
    g_phi[0][idx]          = lin95(q1);
    g_phi[0][NV + idx]     = lin95(q2);
    g_phi[0][2 * NV + idx] = lin95(q3);
}

// gradient (replicate pad) -> grads output slab; u = -res * g -> bufA
__global__ void __launch_bounds__(256) k_grad_u(const float* __restrict__ img,
                                                const float* __restrict__ res,
                                                float* __restrict__ gout) {
    int idx = blockIdx.x * 256 + threadIdx.x;
    if (idx >= NV) return;
    int x = idx % DV, y = (idx / DV) % DV, z = idx / SLB;
    float dx = __fmul_rn(0.5f, __fsub_rn(__ldg(img + idx + (x < DV - 1)),
                                         __ldg(img + idx - (x > 0))));
    float dy = __fmul_rn(0.5f, __fsub_rn(__ldg(img + idx + (y < DV - 1) * DV),
                                         __ldg(img + idx - (y > 0) * DV)));
    float dz = __fmul_rn(0.5f, __fsub_rn(__ldg(img + idx + (z < DV - 1) * SLB),
                                         __ldg(img + idx - (z > 0) * SLB)));
    gout[idx]          = dx;
    gout[NV + idx]     = dy;
    gout[2 * NV + idx] = dz;
    float r = -__ldg(res + idx);
    g_bufA[idx]          = __fmul_rn(r, dx);
    g_bufA[NV + idx]     = __fmul_rn(r, dy);
    g_bufA[2 * NV + idx] = __fmul_rn(r, dz);
}

// smem "pencil" blur along z (AXIS=0) or y (AXIS=1), zero padding.
// Ordered t=0..18 FFMA chain (mirrors a direct fp32 conv).
template<int AXIS, int SI, int DI>
__global__ void __launch_bounds__(256) k_blur_t() {
    const float* src = SI == 0 ? g_bufA : (SI == 1 ? g_bufB : g_bufC);
    float*       dst = DI == 0 ? g_bufA : (DI == 1 ? g_bufB : g_bufC);
    __shared__ float sm[96][32];
    int tx = threadIdx.x;
    int ty = threadIdx.y;
    int xb = blockIdx.x * 32;
    int oc = blockIdx.y;
    int c  = blockIdx.z;
    const int S = (AXIS == 0) ? SLB : DV;
    int base = c * NV + ((AXIS == 0) ? oc * DV : oc * SLB) + xb + tx;

    float gk[19];
#pragma unroll
    for (int t = 0; t < 19; t++) gk[t] = d_GK[t];

#pragma unroll
    for (int a = ty; a < 96; a += 8) sm[a][tx] = __ldg(src + base + a * S);
    __syncthreads();
#pragma unroll
    for (int a = ty; a < 96; a += 8) {
        float acc = 0.f;
#pragma unroll
        for (int t = 0; t < 19; t++) {
            int aa = a + t - 9;
            if (aa >= 0 && aa < 96) acc = fmaf(gk[t], sm[aa][tx], acc);
        }
        dst[base + a * S] = acc;
    }
}

// blur along x; also emits rv = res * v. v -> bufA, rv -> bufB (input bufC)
__global__ void __launch_bounds__(256) k_blurx_rv(const float* __restrict__ res) {
    int idx = blockIdx.x * 256 + threadIdx.x;
    if (idx >= NV3) return;
    int p = idx % NV;
    int x = p % DV;
    float acc = 0.f;
#pragma unroll
    for (int t = 0; t < 19; t++) {
        int aa = x + t - 9;
        if (aa >= 0 && aa < DV) acc = fmaf(d_GK[t], __ldg(g_bufC + idx + (t - 9)), acc);
    }
    g_bufA[idx] = acc;
    g_bufB[idx] = __fmul_rn(__ldg(res + p), acc);
}

// transpose v (bufA, [c][z][y][x]) -> fields slab ([q1][q2][q3][c]),
// fields[q1][q2][q3][c] = v[c][q3][q2][q1]
__global__ void __launch_bounds__(1024) k_fields(float* __restrict__ Fout) {
    __shared__ float tile[3][32][33];
    int tx = threadIdx.x, ty = threadIdx.y;
    int q1b = blockIdx.x * 32;
    int q3b = blockIdx.y * 32;
    int q2  = blockIdx.z;
#pragma unroll
    for (int c = 0; c < 3; c++)
        tile[c][ty][tx] = g_bufA[c * NV + (q3b + ty) * SLB + q2 * DV + (q1b + tx)];
    __syncthreads();
    int ob = ((q1b + ty) * DV + q2) * DV * 3 + (q3b + tx) * 3;
    Fout[ob + 0] = tile[0][tx][ty];
    Fout[ob + 1] = tile[1][tx][ty];
    Fout[ob + 2] = tile[2][tx][ty];
}

// f = div(rv)/L (Sobel/32, zero pad, cross-correlation); res_new = res_old - f
constexpr int TX = 32, TY = 4, TZ = 2;
constexpr int HX = TX + 2, HY = TY + 2, HZ = TZ + 2;   // 34 x 6 x 4
constexpr int HTOT = HX * HY * HZ;                     // 816

__global__ void __launch_bounds__(256) k_div(const float* __restrict__ res_old,
                                             float* __restrict__ res_new) {
    __shared__ float sm[3][HZ][HY][HX];
    int tid = threadIdx.x;
    int xb = (blockIdx.x % 3) * TX;
    int yb = ((blockIdx.x / 3) % (DV / TY)) * TY;
    int zb = (blockIdx.x / (3 * (DV / TY))) * TZ;

    for (int i = tid; i < 3 * HTOT; i += 256) {
        int c  = i / HTOT;
        int r  = i - c * HTOT;
        int lz = r / (HY * HX);
        int r2 = r - lz * (HY * HX);
        int ly = r2 / HX;
        int lx = r2 - ly * HX;
        int gx = xb + lx - 1, gy = yb + ly - 1, gz = zb + lz - 1;
        float v = 0.f;
        if ((unsigned)gx < 96u && (unsigned)gy < 96u && (unsigned)gz < 96u)
            v = __ldg(g_bufB + c * NV + (gz * DV + gy) * DV + gx);
        sm[c][lz][ly][lx] = v;
    }
    __syncthreads();

    int lx = tid % TX;
    int ly = (tid / TX) % TY;
    int lz = tid / (TX * TY);
    int x = xb + lx, y = yb + ly, z = zb + lz;
    int cx = lx + 1, cy = ly + 1, cz = lz + 1;

    float acc = 0.f;
#pragma unroll
    for (int oz = -1; oz <= 1; oz++) {
        float sz = oz ? 1.f : 2.f;
#pragma unroll
        for (int oy = -1; oy <= 1; oy++) {
            float w = sz * (oy ? 1.f : 2.f);
            acc = fmaf(w, sm[0][cz + oz][cy + oy][cx + 1] - sm[0][cz + oz][cy + oy][cx - 1], acc);
        }
    }
#pragma unroll
    for (int oz = -1; oz <= 1; oz++) {
        float sz = oz ? 1.f : 2.f;
#pragma unroll
        for (int ox = -1; ox <= 1; ox++) {
            float w = sz * (ox ? 1.f : 2.f);
            acc = fmaf(w, sm[1][cz + oz][cy + 1][cx + ox] - sm[1][cz + oz][cy - 1][cx + ox], acc);
        }
    }
#pragma unroll
    for (int oy = -1; oy <= 1; oy++) {
        float sy = oy ? 1.f : 2.f;
#pragma unroll
        for (int ox = -1; ox <= 1; ox++) {
            float w = sy * (ox ? 1.f : 2.f);
            acc = fmaf(w, sm[2][cz + 1][cy + oy][cx + ox] - sm[2][cz - 1][cy + oy][cx + ox], acc);
        }
    }

    int idx = (z * DV + y) * DV + x;
    // f = (conv/32)/10 ; res_new = res_old - f  (2^-5 scale is exact)
    float f = __fdiv_rn(__fmul_rn(acc, 0.03125f), 10.0f);
    res_new[idx] = __fsub_rn(__ldg(res_old + idx), f);
}

// fused warp: rd_new[q] = lerp(rd_old, P(q)) + res_new[q]
//             Phi_new[c][q] = lerp(Phi_old[c], P(q))
// P(q): px = def_coord(q3, v0), py = def_coord(q2, v1), pz = def_coord(q1, v2)
__global__ void __launch_bounds__(256) k_deform(const float* __restrict__ F,
                                                const float* __restrict__ resn,
                                                int pi) {
    int idx = blockIdx.x * 256 + threadIdx.x;
    if (idx >= NV) return;
    int q3 = idx % DV, q2 = (idx / DV) % DV, q1 = idx / SLB;
    float F0 = __ldg(F + 3 * idx);
    float F1 = __ldg(F + 3 * idx + 1);
    float F2 = __ldg(F + 3 * idx + 2);
    float px = def_coord(q3, F0);
    float py = def_coord(q2, F1);
    float pz = def_coord(q1, F2);
    int ii[8]; float fx, fy, fz;
    tri_idx(px, py, pz, ii, &fx, &fy, &fz);
    const float* rdO  = g_rd[pi];
    float*       rdN  = g_rd[pi ^ 1];
    const float* phO  = g_phi[pi];
    float*       phN  = g_phi[pi ^ 1];
    rdN[idx] = __fadd_rn(tri_lerp(rdO, ii, fx, fy, fz), __ldg(resn + idx));
#pragma unroll
    for (int c = 0; c < 3; c++)
        phN[c * NV + idx] = tri_lerp(phO + c * NV, ii, fx, fy, fz);
}

// image[z,y,x] = lerp(source, phi) + (rd*0.001)*lerp(seg, phi)
// phi components read at transposed index t=(x*96+y)*96+z
// On the final step, also writes rd to the residuals_deformed output slab.
__global__ void __launch_bounds__(256) k_image(const float* __restrict__ src,
                                               const float* __restrict__ seg,
                                               float* __restrict__ img,
                                               float* __restrict__ rdout,
                                               int pn) {
    int idx = blockIdx.x * 256 + threadIdx.x;
    if (idx >= NV) return;
    int x = idx % DV, y = (idx / DV) % DV, z = idx / SLB;
    int t = (x * DV + y) * DV + z;
    const float* ph = g_phi[pn];
    const float* rd = g_rd[pn];
    float sx = phi_coord(__ldg(ph + t));
    float sy = phi_coord(__ldg(ph + NV + t));
    float sz = phi_coord(__ldg(ph + 2 * NV + t));
    int ii[8]; float fx, fy, fz;
    tri_idx(sx, sy, sz, ii, &fx, &fy, &fz);
    float si = tri_lerp(src, ii, fx, fy, fz);
    float sm = tri_lerp(seg, ii, fx, fy, fz);
    float r = __ldg(rd + idx);
    img[idx] = __fadd_rn(si, __fmul_rn(__fmul_rn(r, 0.001f), sm));  // MU^2/L
    if (rdout) rdout[idx] = r;
}

// ---------------------------------------------------------------------------
extern "C" void kernel_launch(void* const* d_in, const int* in_sizes, int n_in,
                              void* d_out, int out_size) {
    const float* src = (const float*)d_in[0];
    const float* seg = (const float*)d_in[2];
    const float* z0  = (const float*)d_in[3];
    float* out = (float*)d_out;

    float* img     = out;                         // image region doubles as working image
    float* fields0 = out + (long long)NV;
    float* grads0  = fields0 + 10LL * NV3;
    float* res0    = grads0 + 10LL * NV3;
    float* rdout   = res0 + 11LL * NV;

    k_init_gk<<<1, 32>>>();
    k_init_state<<<NV / 256, 256>>>();
    cudaMemcpyAsync(img,  src, (size_t)NV * 4, cudaMemcpyDeviceToDevice, 0);
    cudaMemcpyAsync(res0, z0,  (size_t)NV * 4, cudaMemcpyDeviceToDevice, 0);

    const int divBlocks = 3 * (DV / TY) * (DV / TZ);   // 3456

    for (int i = 0; i < LSTEPS; i++) {
        float* grads      = grads0 + (long long)i * NV3;
        float* fields     = fields0 + (long long)i * NV3;
        const float* ro   = res0 + (long long)i * NV;
        float* rn         = res0 + (long long)(i + 1) * NV;

        k_grad_u<<<NV / 256, 256>>>(img, ro, grads);
        k_blur_t<0, 0, 1><<<dim3(3, 96, 3), dim3(32, 8)>>>();   // z-blur A->B
        k_blur_t<1, 1, 2><<<dim3(3, 96, 3), dim3(32, 8)>>>();   // y-blur B->C
        k_blurx_rv<<<NV3 / 256, 256>>>(ro);                     // x-blur C->A, rv->B
        k_fields<<<dim3(3, 3, 96), dim3(32, 32)>>>(fields);
        k_div<<<divBlocks, 256>>>(ro, rn);
        k_deform<<<NV / 256, 256>>>(fields, rn, i & 1);
        k_image<<<NV / 256, 256>>>(src, seg, img,
                                   (i == LSTEPS - 1) ? rdout : (float*)nullptr,
                                   (i + 1) & 1);
    }
}

// round 10
// speedup vs baseline: 1.2029x; 1.2029x over previous
#include <cuda_runtime.h>

// ---------------------------------------------------------------------------
// metamorphoses shooting, L=10, 96^3, B=1
// ---------------------------------------------------------------------------

constexpr int DV  = 96;
constexpr int SLB = DV * DV;        // 9216
constexpr int NV  = DV * DV * DV;   // 884736
constexpr int NV3 = 3 * NV;
constexpr int LSTEPS = 10;

__device__ float d_GK[19];
__device__ float g_bufA[NV3];       // -res*grad (blur input)
__device__ float g_bufB[NV3];       // z-blur intermediate, then rv
__device__ float g_bufC[NV3];       // y-blur intermediate
__device__ float g_phi[2][NV3];
__device__ float g_rd[2][NV];

// ---------------------------------------------------------------------------
// Bit-exact replicas of the reference's coordinate arithmetic.
__device__ __forceinline__ float lin95(int q) {
    const float DELTA = 2.0f / 95.0f;
    return __fadd_rn(-1.0f, __fmul_rn((float)q, DELTA));
}
__device__ __forceinline__ float def_coord(int q, float v) {
    float d = __fsub_rn(lin95(q), __fdiv_rn(v, 10.0f));
    return __fmul_rn(__fmul_rn(__fadd_rn(d, 1.0f), 0.5f), 95.0f);
}
__device__ __forceinline__ float phi_coord(float g) {
    return __fmul_rn(__fmul_rn(__fadd_rn(g, 1.0f), 0.5f), 95.0f);
}

__device__ __forceinline__ void tri_idx(float px, float py, float pz,
                                        int* ii, float* fx, float* fy, float* fz) {
    float xf = floorf(px), yf = floorf(py), zf = floorf(pz);
    *fx = __fsub_rn(px, xf); *fy = __fsub_rn(py, yf); *fz = __fsub_rn(pz, zf);
    int x0 = (int)xf; x0 = x0 < 0 ? 0 : (x0 > 95 ? 95 : x0); int x1 = x0 < 95 ? x0 + 1 : 95;
    int y0 = (int)yf; y0 = y0 < 0 ? 0 : (y0 > 95 ? 95 : y0); int y1 = y0 < 95 ? y0 + 1 : 95;
    int z0 = (int)zf; z0 = z0 < 0 ? 0 : (z0 > 95 ? 95 : z0); int z1 = z0 < 95 ? z0 + 1 : 95;
    int b00 = (z0 * DV + y0) * DV, b01 = (z0 * DV + y1) * DV;
    int b10 = (z1 * DV + y0) * DV, b11 = (z1 * DV + y1) * DV;
    ii[0] = b00 + x0; ii[1] = b00 + x1; ii[2] = b01 + x0; ii[3] = b01 + x1;
    ii[4] = b10 + x0; ii[5] = b10 + x1; ii[6] = b11 + x0; ii[7] = b11 + x1;
}

__device__ __forceinline__ float tri_lerp(const float* __restrict__ p, const int* ii,
                                          float fx, float fy, float fz) {
    float gx = __fsub_rn(1.0f, fx), gy = __fsub_rn(1.0f, fy), gz = __fsub_rn(1.0f, fz);
    float c000 = __ldg(p + ii[0]), c001 = __ldg(p + ii[1]);
    float c010 = __ldg(p + ii[2]), c011 = __ldg(p + ii[3]);
    float c100 = __ldg(p + ii[4]), c101 = __ldg(p + ii[5]);
    float c110 = __ldg(p + ii[6]), c111 = __ldg(p + ii[7]);
    float a0 = __fadd_rn(__fmul_rn(c000, gx), __fmul_rn(c001, fx));
    float a1 = __fadd_rn(__fmul_rn(c010, gx), __fmul_rn(c011, fx));
    float lo = __fadd_rn(__fmul_rn(a0, gy), __fmul_rn(a1, fy));
    float b0 = __fadd_rn(__fmul_rn(c100, gx), __fmul_rn(c101, fx));
    float b1 = __fadd_rn(__fmul_rn(c110, gx), __fmul_rn(c111, fx));
    float hi = __fadd_rn(__fmul_rn(b0, gy), __fmul_rn(b1, fy));
    return __fadd_rn(__fmul_rn(lo, gz), __fmul_rn(hi, fz));
}

// ---------------------------------------------------------------------------
__global__ void k_init_gk() {
    if (threadIdx.x == 0 && blockIdx.x == 0) {
        float v[19]; float s = 0.f;
        for (int i = 0; i < 19; i++) {
            float x = (float)(i - 9) / 3.0f;
            v[i] = expf(-0.5f * x * x);
            s += v[i];
        }
        for (int i = 0; i < 19; i++) d_GK[i] = __fdiv_rn(v[i], s);
    }
}

__global__ void __launch_bounds__(256) k_init_state() {
    int idx = blockIdx.x * 256 + threadIdx.x;
    if (idx >= NV) return;
    int q3 = idx % DV, q2 = (idx / DV) % DV, q1 = idx / SLB;
    g_rd[0][idx] = 0.f;
    g_phi[0][idx]          = lin95(q1);
    g_phi[0][NV + idx]     = lin95(q2);
    g_phi[0][2 * NV + idx] = lin95(q3);
}

// gradient (replicate pad), float4: 4 x-values per thread.
// grads -> output slab; u = -res*g -> bufA
__global__ void __launch_bounds__(256) k_grad_u4(const float* __restrict__ img,
                                                 const float* __restrict__ res,
                                                 float* __restrict__ gout) {
    int tid = blockIdx.x * 256 + threadIdx.x;
    if (tid >= NV / 4) return;
    int x4 = (tid % 24) * 4;
    int y  = (tid / 24) % DV;
    int z  = tid / (24 * DV);
    int base = z * SLB + y * DV + x4;

    float4 v  = *(const float4*)(img + base);
    float  lm = (x4 > 0)  ? __ldg(img + base - 1) : v.x;
    float  rp = (x4 < 92) ? __ldg(img + base + 4) : v.w;
    float4 up = (y > 0)  ? *(const float4*)(img + base - DV)  : v;
    float4 dn = (y < 95) ? *(const float4*)(img + base + DV)  : v;
    float4 fr = (z > 0)  ? *(const float4*)(img + base - SLB) : v;
    float4 bk = (z < 95) ? *(const float4*)(img + base + SLB) : v;

    float4 dx, dy, dz;
    dx.x = __fmul_rn(0.5f, __fsub_rn(v.y, lm));
    dx.y = __fmul_rn(0.5f, __fsub_rn(v.z, v.x));
    dx.z = __fmul_rn(0.5f, __fsub_rn(v.w, v.y));
    dx.w = __fmul_rn(0.5f, __fsub_rn(rp, v.z));
    dy.x = __fmul_rn(0.5f, __fsub_rn(dn.x, up.x));
    dy.y = __fmul_rn(0.5f, __fsub_rn(dn.y, up.y));
    dy.z = __fmul_rn(0.5f, __fsub_rn(dn.z, up.z));
    dy.w = __fmul_rn(0.5f, __fsub_rn(dn.w, up.w));
    dz.x = __fmul_rn(0.5f, __fsub_rn(bk.x, fr.x));
    dz.y = __fmul_rn(0.5f, __fsub_rn(bk.y, fr.y));
    dz.z = __fmul_rn(0.5f, __fsub_rn(bk.z, fr.z));
    dz.w = __fmul_rn(0.5f, __fsub_rn(bk.w, fr.w));

    *(float4*)(gout + base)          = dx;
    *(float4*)(gout + NV + base)     = dy;
    *(float4*)(gout + 2 * NV + base) = dz;

    float4 r4 = *(const float4*)(res + base);
    float4 u0, u1, u2;
    u0.x = __fmul_rn(-r4.x, dx.x); u0.y = __fmul_rn(-r4.y, dx.y);
    u0.z = __fmul_rn(-r4.z, dx.z); u0.w = __fmul_rn(-r4.w, dx.w);
    u1.x = __fmul_rn(-r4.x, dy.x); u1.y = __fmul_rn(-r4.y, dy.y);
    u1.z = __fmul_rn(-r4.z, dy.z); u1.w = __fmul_rn(-r4.w, dy.w);
    u2.x = __fmul_rn(-r4.x, dz.x); u2.y = __fmul_rn(-r4.y, dz.y);
    u2.z = __fmul_rn(-r4.z, dz.z); u2.w = __fmul_rn(-r4.w, dz.w);
    *(float4*)(g_bufA + base)          = u0;
    *(float4*)(g_bufA + NV + base)     = u1;
    *(float4*)(g_bufA + 2 * NV + base) = u2;
}

// Register sliding-window blur along z (AXIS=0) or y (AXIS=1). Zero pad.
// Thread: 12 consecutive outputs, 30-float window, 12 independent accumulators.
// fmaf(g,0,acc)==acc -> bit-identical to the conditional-tap version.
template<int AXIS, int SI, int DI>
__global__ void __launch_bounds__(256) k_blur_reg() {
    const float* src = SI == 0 ? g_bufA : (SI == 1 ? g_bufB : g_bufC);
    float*       dst = DI == 0 ? g_bufA : (DI == 1 ? g_bufB : g_bufC);
    int tx = threadIdx.x, ty = threadIdx.y;
    int xb = blockIdx.x * 32, oc = blockIdx.y, c = blockIdx.z;
    const int S = (AXIS == 0) ? SLB : DV;
    int base = c * NV + ((AXIS == 0) ? oc * DV : oc * SLB) + xb + tx;
    int a0 = ty * 12;

    float in[30];
#pragma unroll
    for (int k = 0; k < 30; k++) {
        int m = a0 - 9 + k;
        in[k] = ((unsigned)m < 96u) ? __ldg(src + base + m * S) : 0.f;
    }
    float acc[12];
#pragma unroll
    for (int j = 0; j < 12; j++) acc[j] = 0.f;
#pragma unroll
    for (int t = 0; t < 19; t++) {
        float g = __ldg(d_GK + t);
#pragma unroll
        for (int j = 0; j < 12; j++) acc[j] = fmaf(g, in[j + t], acc[j]);
    }
#pragma unroll
    for (int j = 0; j < 12; j++) dst[base + (a0 + j) * S] = acc[j];
}

// x-blur (from bufC) + rv = res*v -> bufB + fields transpose write.
// Block: 32x * 32z tile, fixed y, all 3 channels.
__global__ void __launch_bounds__(256) k_blurx_rv_fields(const float* __restrict__ res,
                                                         float* __restrict__ Fout) {
    __shared__ float sIn[3][32][50];
    __shared__ float sV[32][97];     // [xx][zz*3+c], pad to 97 (conflict-free)
    int tid = threadIdx.x;
    int xb = blockIdx.x * 32, y = blockIdx.y, zb = blockIdx.z * 32;

    for (int i = tid; i < 3 * 32 * 50; i += 256) {
        int c = i / (32 * 50); int r = i % (32 * 50);
        int zz = r / 50; int dxx = r % 50;
        int gx = xb + dxx - 9;
        float v = 0.f;
        if ((unsigned)gx < 96u)
            v = __ldg(g_bufC + c * NV + (zb + zz) * SLB + y * DV + gx);
        sIn[c][zz][dxx] = v;
    }
    __syncthreads();

#pragma unroll
    for (int p = 0; p < 4; p++) {
        int lin = tid + p * 256;
        int zz = lin / 32, xx = lin % 32;
        int gidx = (zb + zz) * SLB + y * DV + xb + xx;
        float r = __ldg(res + gidx);
#pragma unroll
        for (int c = 0; c < 3; c++) {
            float acc = 0.f;
#pragma unroll
            for (int t = 0; t < 19; t++)
                acc = fmaf(__ldg(d_GK + t), sIn[c][zz][xx + t], acc);
            g_bufB[c * NV + gidx] = __fmul_rn(r, acc);
            sV[xx][zz * 3 + c] = acc;
        }
    }
    __syncthreads();

    // fields[q1=x][q2=y][q3=z][c]: contiguous run of 96 floats per (x,y)
    for (int i = tid; i < 3072; i += 256) {
        int xx = i / 96, rr = i % 96;
        Fout[(((xb + xx) * DV + y) * DV + zb) * 3 + rr] = sV[xx][rr];
    }
}

// Fused: f = div(rv)/L ; res_new = res_old - f ; then warp rd & phi with res_new.
constexpr int TX = 32, TY = 4, TZ = 2;
constexpr int HX = TX + 2, HY = TY + 2, HZ = TZ + 2;
constexpr int HTOT = HX * HY * HZ;

__global__ void __launch_bounds__(256) k_div_deform(const float* __restrict__ res_old,
                                                    float* __restrict__ res_new,
                                                    const float* __restrict__ F,
                                                    int pi) {
    __shared__ float sm[3][HZ][HY][HX];
    int tid = threadIdx.x;
    int xb = (blockIdx.x % 3) * TX;
    int yb = ((blockIdx.x / 3) % (DV / TY)) * TY;
    int zb = (blockIdx.x / (3 * (DV / TY))) * TZ;

    for (int i = tid; i < 3 * HTOT; i += 256) {
        int c  = i / HTOT;
        int r  = i - c * HTOT;
        int lz = r / (HY * HX);
        int r2 = r - lz * (HY * HX);
        int ly = r2 / HX;
        int lx = r2 - ly * HX;
        int gx = xb + lx - 1, gy = yb + ly - 1, gz = zb + lz - 1;
        float v = 0.f;
        if ((unsigned)gx < 96u && (unsigned)gy < 96u && (unsigned)gz < 96u)
            v = __ldg(g_bufB + c * NV + (gz * DV + gy) * DV + gx);
        sm[c][lz][ly][lx] = v;
    }
    __syncthreads();

    int lx = tid % TX;
    int ly = (tid / TX) % TY;
    int lz = tid / (TX * TY);
    int x = xb + lx, y = yb + ly, z = zb + lz;
    int cx = lx + 1, cy = ly + 1, cz = lz + 1;

    float acc = 0.f;
#pragma unroll
    for (int oz = -1; oz <= 1; oz++) {
        float sz = oz ? 1.f : 2.f;
#pragma unroll
        for (int oy = -1; oy <= 1; oy++) {
            float w = sz * (oy ? 1.f : 2.f);
            acc = fmaf(w, sm[0][cz + oz][cy + oy][cx + 1] - sm[0][cz + oz][cy + oy][cx - 1], acc);
        }
    }
#pragma unroll
    for (int oz = -1; oz <= 1; oz++) {
        float sz = oz ? 1.f : 2.f;
#pragma unroll
        for (int ox = -1; ox <= 1; ox++) {
            float w = sz * (ox ? 1.f : 2.f);
            acc = fmaf(w, sm[1][cz + oz][cy + 1][cx + ox] - sm[1][cz + oz][cy - 1][cx + ox], acc);
        }
    }
#pragma unroll
    for (int oy = -1; oy <= 1; oy++) {
        float sy = oy ? 1.f : 2.f;
#pragma unroll
        for (int ox = -1; ox <= 1; ox++) {
            float w = sy * (ox ? 1.f : 2.f);
            acc = fmaf(w, sm[2][cz + 1][cy + oy][cx + ox] - sm[2][cz - 1][cy + oy][cx + ox], acc);
        }
    }

    int idx = (z * DV + y) * DV + x;
    float f = __fdiv_rn(__fmul_rn(acc, 0.03125f), 10.0f);
    float resn = __fsub_rn(__ldg(res_old + idx), f);
    res_new[idx] = resn;

    // ---- deform (idx = (q1*96+q2)*96+q3 with q1=z, q2=y, q3=x) ----
    float F0 = __ldg(F + 3 * idx);
    float F1 = __ldg(F + 3 * idx + 1);
    float F2 = __ldg(F + 3 * idx + 2);
    float px = def_coord(x, F0);
    float py = def_coord(y, F1);
    float pz = def_coord(z, F2);
    int ii[8]; float fx, fy, fz;
    tri_idx(px, py, pz, ii, &fx, &fy, &fz);
    const float* rdO = g_rd[pi];
    float*       rdN = g_rd[pi ^ 1];
    const float* phO = g_phi[pi];
    float*       phN = g_phi[pi ^ 1];
    rdN[idx] = __fadd_rn(tri_lerp(rdO, ii, fx, fy, fz), resn);
#pragma unroll
    for (int c = 0; c < 3; c++)
        phN[c * NV + idx] = tri_lerp(phO + c * NV, ii, fx, fy, fz);
}

// image with smem tile transpose for the phi reads.
// Block: 32x * 32z tile, fixed y.
__global__ void __launch_bounds__(256) k_image_t(const float* __restrict__ src,
                                                 const float* __restrict__ seg,
                                                 float* __restrict__ img,
                                                 float* __restrict__ rdout,
                                                 int pn) {
    __shared__ float sPh[3][32][33];
    int tid = threadIdx.x;
    int xb = blockIdx.x * 32, y = blockIdx.y, zb = blockIdx.z * 32;
    const float* ph = g_phi[pn];

    for (int i = tid; i < 3 * 32 * 32; i += 256) {
        int c = i / 1024; int r = i % 1024;
        int xx = r / 32; int zz = r % 32;
        sPh[c][xx][zz] = __ldg(ph + c * NV + ((xb + xx) * DV + y) * DV + zb + zz);
    }
    __syncthreads();

    const float* rd = g_rd[pn];
#pragma unroll
    for (int p = 0; p < 4; p++) {
        int lin = tid + p * 256;
        int xx = lin % 32, zz = lin / 32;
        float sx = phi_coord(sPh[0][xx][zz]);
        float sy = phi_coord(sPh[1][xx][zz]);
        float sz = phi_coord(sPh[2][xx][zz]);
        int ii[8]; float fx, fy, fz;
        tri_idx(sx, sy, sz, ii, &fx, &fy, &fz);
        float si  = tri_lerp(src, ii, fx, fy, fz);
        float smv = tri_lerp(seg, ii, fx, fy, fz);
        int idx = (zb + zz) * SLB + y * DV + xb + xx;
        float r = __ldg(rd + idx);
        img[idx] = __fadd_rn(si, __fmul_rn(__fmul_rn(r, 0.001f), smv));
        if (rdout) rdout[idx] = r;
    }
}

// ---------------------------------------------------------------------------
extern "C" void kernel_launch(void* const* d_in, const int* in_sizes, int n_in,
                              void* d_out, int out_size) {
    const float* src = (const float*)d_in[0];
    const float* seg = (const float*)d_in[2];
    const float* z0  = (const float*)d_in[3];
    float* out = (float*)d_out;

    float* img     = out;
    float* fields0 = out + (long long)NV;
    float* grads0  = fields0 + 10LL * NV3;
    float* res0    = grads0 + 10LL * NV3;
    float* rdout   = res0 + 11LL * NV;

    k_init_gk<<<1, 32>>>();
    k_init_state<<<NV / 256, 256>>>();
    cudaMemcpyAsync(img,  src, (size_t)NV * 4, cudaMemcpyDeviceToDevice, 0);
    cudaMemcpyAsync(res0, z0,  (size_t)NV * 4, cudaMemcpyDeviceToDevice, 0);

    const int divBlocks = 3 * (DV / TY) * (DV / TZ);   // 3456

    for (int i = 0; i < LSTEPS; i++) {
        float* grads      = grads0 + (long long)i * NV3;
        float* fields     = fields0 + (long long)i * NV3;
        const float* ro   = res0 + (long long)i * NV;
        float* rn         = res0 + (long long)(i + 1) * NV;

        k_grad_u4<<<NV / 4 / 256, 256>>>(img, ro, grads);
        k_blur_reg<0, 0, 1><<<dim3(3, 96, 3), dim3(32, 8)>>>();   // z-blur A->B
        k_blur_reg<1, 1, 2><<<dim3(3, 96, 3), dim3(32, 8)>>>();   // y-blur B->C
        k_blurx_rv_fields<<<dim3(3, 96, 3), 256>>>(ro, fields);   // x-blur C->rv(B)+fields
        k_div_deform<<<divBlocks, 256>>>(ro, rn, fields, i & 1);
        k_image_t<<<dim3(3, 96, 3), 256>>>(src, seg, img,
                                           (i == LSTEPS - 1) ? rdout : (float*)nullptr,
                                           (i + 1) & 1);
    }
}

// round 11
// speedup vs baseline: 1.2994x; 1.0802x over previous
#include <cuda_runtime.h>

// ---------------------------------------------------------------------------
// metamorphoses shooting, L=10, 96^3, B=1
// ---------------------------------------------------------------------------

constexpr int DV  = 96;
constexpr int SLB = DV * DV;        // 9216
constexpr int NV  = DV * DV * DV;   // 884736
constexpr int NV3 = 3 * NV;
constexpr int LSTEPS = 10;

__device__ float  d_GK[19];
__device__ float  g_bufB[NV3];      // z-blurred u, later rv
__device__ float  g_bufC[NV3];      // y-blurred
__device__ float4 g_state[2][NV];   // .x=rd, .y=phi_x, .z=phi_y, .w=phi_z
__device__ float2 g_srcseg[NV];     // packed (source, seg)

// ---------------------------------------------------------------------------
// Bit-exact replicas of the reference's coordinate arithmetic.
__device__ __forceinline__ float lin95(int q) {
    const float DELTA = 2.0f / 95.0f;
    return __fadd_rn(-1.0f, __fmul_rn((float)q, DELTA));
}
__device__ __forceinline__ float def_coord(int q, float v) {
    float d = __fsub_rn(lin95(q), __fdiv_rn(v, 10.0f));
    return __fmul_rn(__fmul_rn(__fadd_rn(d, 1.0f), 0.5f), 95.0f);
}
__device__ __forceinline__ float phi_coord(float g) {
    return __fmul_rn(__fmul_rn(__fadd_rn(g, 1.0f), 0.5f), 95.0f);
}

__device__ __forceinline__ void tri_idx(float px, float py, float pz,
                                        int* ii, float* fx, float* fy, float* fz) {
    float xf = floorf(px), yf = floorf(py), zf = floorf(pz);
    *fx = __fsub_rn(px, xf); *fy = __fsub_rn(py, yf); *fz = __fsub_rn(pz, zf);
    int x0 = (int)xf; x0 = x0 < 0 ? 0 : (x0 > 95 ? 95 : x0); int x1 = x0 < 95 ? x0 + 1 : 95;
    int y0 = (int)yf; y0 = y0 < 0 ? 0 : (y0 > 95 ? 95 : y0); int y1 = y0 < 95 ? y0 + 1 : 95;
    int z0 = (int)zf; z0 = z0 < 0 ? 0 : (z0 > 95 ? 95 : z0); int z1 = z0 < 95 ? z0 + 1 : 95;
    int b00 = (z0 * DV + y0) * DV, b01 = (z0 * DV + y1) * DV;
    int b10 = (z1 * DV + y0) * DV, b11 = (z1 * DV + y1) * DV;
    ii[0] = b00 + x0; ii[1] = b00 + x1; ii[2] = b01 + x0; ii[3] = b01 + x1;
    ii[4] = b10 + x0; ii[5] = b10 + x1; ii[6] = b11 + x0; ii[7] = b11 + x1;
}

// reference's exact nested-lerp op order on 8 scalars
__device__ __forceinline__ float lerp8(float c000, float c001, float c010, float c011,
                                       float c100, float c101, float c110, float c111,
                                       float fx, float fy, float fz,
                                       float gx, float gy, float gz) {
    float a0 = __fadd_rn(__fmul_rn(c000, gx), __fmul_rn(c001, fx));
    float a1 = __fadd_rn(__fmul_rn(c010, gx), __fmul_rn(c011, fx));
    float lo = __fadd_rn(__fmul_rn(a0, gy), __fmul_rn(a1, fy));
    float b0 = __fadd_rn(__fmul_rn(c100, gx), __fmul_rn(c101, fx));
    float b1 = __fadd_rn(__fmul_rn(c110, gx), __fmul_rn(c111, fx));
    float hi = __fadd_rn(__fmul_rn(b0, gy), __fmul_rn(b1, fy));
    return __fadd_rn(__fmul_rn(lo, gz), __fmul_rn(hi, fz));
}

// ---------------------------------------------------------------------------
__global__ void k_init_gk() {
    if (threadIdx.x == 0 && blockIdx.x == 0) {
        float v[19]; float s = 0.f;
        for (int i = 0; i < 19; i++) {
            float x = (float)(i - 9) / 3.0f;
            v[i] = expf(-0.5f * x * x);
            s += v[i];
        }
        for (int i = 0; i < 19; i++) d_GK[i] = __fdiv_rn(v[i], s);
    }
}

__global__ void __launch_bounds__(256) k_init_state(const float* __restrict__ src,
                                                    const float* __restrict__ seg) {
    int idx = blockIdx.x * 256 + threadIdx.x;
    if (idx >= NV) return;
    int q3 = idx % DV, q2 = (idx / DV) % DV, q1 = idx / SLB;
    g_state[0][idx] = make_float4(0.f, lin95(q1), lin95(q2), lin95(q3));
    g_srcseg[idx]   = make_float2(__ldg(src + idx), __ldg(seg + idx));
}

// Fused gradient + z-blur. One channel per blockIdx.z.
// Computes u = -res * grad_c over the pencil window, writes grads slab for the
// 12 output z's, blurs u along z (zero pad) into bufB. Bit-identical to the
// separate grad + blur kernels.
__global__ void __launch_bounds__(256) k_gradblur(const float* __restrict__ img,
                                                  const float* __restrict__ res,
                                                  float* __restrict__ gout) {
    int tx = threadIdx.x, ty = threadIdx.y;
    int xb = blockIdx.x * 32, y = blockIdx.y, c = blockIdx.z;
    int x = xb + tx;
    int base = y * DV + x;          // z = 0
    int a0 = ty * 12;

    float u[30];
    if (c == 0) {
        int op = (x < 95) ? 1 : 0, om = (x > 0) ? 1 : 0;
#pragma unroll
        for (int k = 0; k < 30; k++) {
            int z = a0 - 9 + k;
            if ((unsigned)z < 96u) {
                int p = base + z * SLB;
                float g = __fmul_rn(0.5f, __fsub_rn(__ldg(img + p + op), __ldg(img + p - om)));
                if (k >= 9 && k < 21) gout[p] = g;
                float r = -__ldg(res + p);
                u[k] = __fmul_rn(r, g);
            } else u[k] = 0.f;
        }
    } else if (c == 1) {
        int op = (y < 95) ? DV : 0, om = (y > 0) ? DV : 0;
#pragma unroll
        for (int k = 0; k < 30; k++) {
            int z = a0 - 9 + k;
            if ((unsigned)z < 96u) {
                int p = base + z * SLB;
                float g = __fmul_rn(0.5f, __fsub_rn(__ldg(img + p + op), __ldg(img + p - om)));
                if (k >= 9 && k < 21) gout[NV + p] = g;
                float r = -__ldg(res + p);
                u[k] = __fmul_rn(r, g);
            } else u[k] = 0.f;
        }
    } else {
#pragma unroll
        for (int k = 0; k < 30; k++) {
            int z = a0 - 9 + k;
            if ((unsigned)z < 96u) {
                int p = base + z * SLB;
                int op = (z < 95) ? SLB : 0, om = (z > 0) ? SLB : 0;
                float g = __fmul_rn(0.5f, __fsub_rn(__ldg(img + p + op), __ldg(img + p - om)));
                if (k >= 9 && k < 21) gout[2 * NV + p] = g;
                float r = -__ldg(res + p);
                u[k] = __fmul_rn(r, g);
            } else u[k] = 0.f;
        }
    }

    float acc[12];
#pragma unroll
    for (int j = 0; j < 12; j++) acc[j] = 0.f;
#pragma unroll
    for (int t = 0; t < 19; t++) {
        float g = __ldg(d_GK + t);
#pragma unroll
        for (int j = 0; j < 12; j++) acc[j] = fmaf(g, u[j + t], acc[j]);
    }
#pragma unroll
    for (int j = 0; j < 12; j++) g_bufB[c * NV + base + (a0 + j) * SLB] = acc[j];
}

// Register sliding-window y-blur, bufB -> bufC. Zero pad, bit-identical.
__global__ void __launch_bounds__(256) k_blur_y() {
    int tx = threadIdx.x, ty = threadIdx.y;
    int xb = blockIdx.x * 32, z = blockIdx.y, c = blockIdx.z;
    int base = c * NV + z * SLB + xb + tx;
    int a0 = ty * 12;

    float in[30];
#pragma unroll
    for (int k = 0; k < 30; k++) {
        int m = a0 - 9 + k;
        in[k] = ((unsigned)m < 96u) ? __ldg(g_bufB + base + m * DV) : 0.f;
    }
    float acc[12];
#pragma unroll
    for (int j = 0; j < 12; j++) acc[j] = 0.f;
#pragma unroll
    for (int t = 0; t < 19; t++) {
        float g = __ldg(d_GK + t);
#pragma unroll
        for (int j = 0; j < 12; j++) acc[j] = fmaf(g, in[j + t], acc[j]);
    }
#pragma unroll
    for (int j = 0; j < 12; j++) g_bufC[base + (a0 + j) * DV] = acc[j];
}

// x-blur (from bufC) + rv = res*v -> bufB + fields transpose write.
__global__ void __launch_bounds__(256) k_blurx_rv_fields(const float* __restrict__ res,
                                                         float* __restrict__ Fout) {
    __shared__ float sIn[3][32][50];
    __shared__ float sV[32][97];
    int tid = threadIdx.x;
    int xb = blockIdx.x * 32, y = blockIdx.y, zb = blockIdx.z * 32;

    for (int i = tid; i < 3 * 32 * 50; i += 256) {
        int c = i / (32 * 50); int r = i % (32 * 50);
        int zz = r / 50; int dxx = r % 50;
        int gx = xb + dxx - 9;
        float v = 0.f;
        if ((unsigned)gx < 96u)
            v = __ldg(g_bufC + c * NV + (zb + zz) * SLB + y * DV + gx);
        sIn[c][zz][dxx] = v;
    }
    __syncthreads();

#pragma unroll
    for (int p = 0; p < 4; p++) {
        int lin = tid + p * 256;
        int zz = lin / 32, xx = lin % 32;
        int gidx = (zb + zz) * SLB + y * DV + xb + xx;
        float r = __ldg(res + gidx);
#pragma unroll
        for (int c = 0; c < 3; c++) {
            float acc = 0.f;
#pragma unroll
            for (int t = 0; t < 19; t++)
                acc = fmaf(__ldg(d_GK + t), sIn[c][zz][xx + t], acc);
            g_bufB[c * NV + gidx] = __fmul_rn(r, acc);
            sV[xx][zz * 3 + c] = acc;
        }
    }
    __syncthreads();

    for (int i = tid; i < 3072; i += 256) {
        int xx = i / 96, rr = i % 96;
        Fout[(((xb + xx) * DV + y) * DV + zb) * 3 + rr] = sV[xx][rr];
    }
}

// Fused: f = div(rv)/L ; res_new ; warp packed state (rd,phi) via float4 gathers.
constexpr int TX = 32, TY = 4, TZ = 2;
constexpr int HX = TX + 2, HY = TY + 2, HZ = TZ + 2;
constexpr int HTOT = HX * HY * HZ;

__global__ void __launch_bounds__(256) k_div_deform(const float* __restrict__ res_old,
                                                    float* __restrict__ res_new,
                                                    const float* __restrict__ F,
                                                    int pi) {
    __shared__ float sm[3][HZ][HY][HX];
    int tid = threadIdx.x;
    int xb = (blockIdx.x % 3) * TX;
    int yb = ((blockIdx.x / 3) % (DV / TY)) * TY;
    int zb = (blockIdx.x / (3 * (DV / TY))) * TZ;

    for (int i = tid; i < 3 * HTOT; i += 256) {
        int c  = i / HTOT;
        int r  = i - c * HTOT;
        int lz = r / (HY * HX);
        int r2 = r - lz * (HY * HX);
        int ly = r2 / HX;
        int lx = r2 - ly * HX;
        int gx = xb + lx - 1, gy = yb + ly - 1, gz = zb + lz - 1;
        float v = 0.f;
        if ((unsigned)gx < 96u && (unsigned)gy < 96u && (unsigned)gz < 96u)
            v = __ldg(g_bufB + c * NV + (gz * DV + gy) * DV + gx);
        sm[c][lz][ly][lx] = v;
    }
    __syncthreads();

    int lx = tid % TX;
    int ly = (tid / TX) % TY;
    int lz = tid / (TX * TY);
    int x = xb + lx, y = yb + ly, z = zb + lz;
    int cx = lx + 1, cy = ly + 1, cz = lz + 1;

    float acc = 0.f;
#pragma unroll
    for (int oz = -1; oz <= 1; oz++) {
        float sz = oz ? 1.f : 2.f;
#pragma unroll
        for (int oy = -1; oy <= 1; oy++) {
            float w = sz * (oy ? 1.f : 2.f);
            acc = fmaf(w, sm[0][cz + oz][cy + oy][cx + 1] - sm[0][cz + oz][cy + oy][cx - 1], acc);
        }
    }
#pragma unroll
    for (int oz = -1; oz <= 1; oz++) {
        float sz = oz ? 1.f : 2.f;
#pragma unroll
        for (int ox = -1; ox <= 1; ox++) {
            float w = sz * (ox ? 1.f : 2.f);
            acc = fmaf(w, sm[1][cz + oz][cy + 1][cx + ox] - sm[1][cz + oz][cy - 1][cx + ox], acc);
        }
    }
#pragma unroll
    for (int oy = -1; oy <= 1; oy++) {
        float sy = oy ? 1.f : 2.f;
#pragma unroll
        for (int ox = -1; ox <= 1; ox++) {
            float w = sy * (ox ? 1.f : 2.f);
            acc = fmaf(w, sm[2][cz + 1][cy + oy][cx + ox] - sm[2][cz - 1][cy + oy][cx + ox], acc);
        }
    }

    int idx = (z * DV + y) * DV + x;
    float f = __fdiv_rn(__fmul_rn(acc, 0.03125f), 10.0f);
    float resn = __fsub_rn(__ldg(res_old + idx), f);
    res_new[idx] = resn;

    // ---- deform via packed float4 state ----
    float F0 = __ldg(F + 3 * idx);
    float F1 = __ldg(F + 3 * idx + 1);
    float F2 = __ldg(F + 3 * idx + 2);
    float px = def_coord(x, F0);
    float py = def_coord(y, F1);
    float pz = def_coord(z, F2);
    int ii[8]; float fx, fy, fz;
    tri_idx(px, py, pz, ii, &fx, &fy, &fz);
    float gx = __fsub_rn(1.0f, fx), gy = __fsub_rn(1.0f, fy), gz = __fsub_rn(1.0f, fz);

    const float4* stO = g_state[pi];
    float4*       stN = g_state[pi ^ 1];
    float4 c000 = __ldg(stO + ii[0]), c001 = __ldg(stO + ii[1]);
    float4 c010 = __ldg(stO + ii[2]), c011 = __ldg(stO + ii[3]);
    float4 c100 = __ldg(stO + ii[4]), c101 = __ldg(stO + ii[5]);
    float4 c110 = __ldg(stO + ii[6]), c111 = __ldg(stO + ii[7]);

    float rdw = lerp8(c000.x, c001.x, c010.x, c011.x, c100.x, c101.x, c110.x, c111.x,
                      fx, fy, fz, gx, gy, gz);
    float p0  = lerp8(c000.y, c001.y, c010.y, c011.y, c100.y, c101.y, c110.y, c111.y,
                      fx, fy, fz, gx, gy, gz);
    float p1  = lerp8(c000.z, c001.z, c010.z, c011.z, c100.z, c101.z, c110.z, c111.z,
                      fx, fy, fz, gx, gy, gz);
    float p2  = lerp8(c000.w, c001.w, c010.w, c011.w, c100.w, c101.w, c110.w, c111.w,
                      fx, fy, fz, gx, gy, gz);
    stN[idx] = make_float4(__fadd_rn(rdw, resn), p0, p1, p2);
}

// image: sample packed (src,seg) at phi; phi read transposed via smem tiles.
__global__ void __launch_bounds__(256) k_image_t(float* __restrict__ img,
                                                 float* __restrict__ rdout,
                                                 int pn) {
    __shared__ float sPh[3][32][33];
    int tid = threadIdx.x;
    int xb = blockIdx.x * 32, y = blockIdx.y, zb = blockIdx.z * 32;
    const float4* st = g_state[pn];

    for (int i = tid; i < 32 * 32; i += 256) {
        int xx = i / 32, zz = i % 32;
        float4 q = __ldg(st + ((xb + xx) * DV + y) * DV + zb + zz);
        sPh[0][xx][zz] = q.y;
        sPh[1][xx][zz] = q.z;
        sPh[2][xx][zz] = q.w;
    }
    __syncthreads();

#pragma unroll
    for (int p = 0; p < 4; p++) {
        int lin = tid + p * 256;
        int xx = lin % 32, zz = lin / 32;
        float sx = phi_coord(sPh[0][xx][zz]);
        float sy = phi_coord(sPh[1][xx][zz]);
        float sz = phi_coord(sPh[2][xx][zz]);
        int ii[8]; float fx, fy, fz;
        tri_idx(sx, sy, sz, ii, &fx, &fy, &fz);
        float gx = __fsub_rn(1.0f, fx), gy = __fsub_rn(1.0f, fy), gz = __fsub_rn(1.0f, fz);
        float2 c000 = __ldg(g_srcseg + ii[0]), c001 = __ldg(g_srcseg + ii[1]);
        float2 c010 = __ldg(g_srcseg + ii[2]), c011 = __ldg(g_srcseg + ii[3]);
        float2 c100 = __ldg(g_srcseg + ii[4]), c101 = __ldg(g_srcseg + ii[5]);
        float2 c110 = __ldg(g_srcseg + ii[6]), c111 = __ldg(g_srcseg + ii[7]);
        float si  = lerp8(c000.x, c001.x, c010.x, c011.x, c100.x, c101.x, c110.x, c111.x,
                          fx, fy, fz, gx, gy, gz);
        float smv = lerp8(c000.y, c001.y, c010.y, c011.y, c100.y, c101.y, c110.y, c111.y,
                          fx, fy, fz, gx, gy, gz);
        int idx = (zb + zz) * SLB + y * DV + xb + xx;
        float r = __ldg((const float*)(st + idx));   // .x lane
        img[idx] = __fadd_rn(si, __fmul_rn(__fmul_rn(r, 0.001f), smv));
        if (rdout) rdout[idx] = r;
    }
}

// ---------------------------------------------------------------------------
extern "C" void kernel_launch(void* const* d_in, const int* in_sizes, int n_in,
                              void* d_out, int out_size) {
    const float* src = (const float*)d_in[0];
    const float* seg = (const float*)d_in[2];
    const float* z0  = (const float*)d_in[3];
    float* out = (float*)d_out;

    float* img     = out;
    float* fields0 = out + (long long)NV;
    float* grads0  = fields0 + 10LL * NV3;
    float* res0    = grads0 + 10LL * NV3;
    float* rdout   = res0 + 11LL * NV;

    k_init_gk<<<1, 32>>>();
    k_init_state<<<NV / 256, 256>>>(src, seg);
    cudaMemcpyAsync(img,  src, (size_t)NV * 4, cudaMemcpyDeviceToDevice, 0);
    cudaMemcpyAsync(res0, z0,  (size_t)NV * 4, cudaMemcpyDeviceToDevice, 0);

    const int divBlocks = 3 * (DV / TY) * (DV / TZ);   // 3456

    for (int i = 0; i < LSTEPS; i++) {
        float* grads      = grads0 + (long long)i * NV3;
        float* fields     = fields0 + (long long)i * NV3;
        const float* ro   = res0 + (long long)i * NV;
        float* rn         = res0 + (long long)(i + 1) * NV;

        k_gradblur<<<dim3(3, 96, 3), dim3(32, 8)>>>(img, ro, grads);   // grad+z-blur -> B
        k_blur_y<<<dim3(3, 96, 3), dim3(32, 8)>>>();                   // y-blur B -> C
        k_blurx_rv_fields<<<dim3(3, 96, 3), 256>>>(ro, fields);        // x-blur C -> rv(B)+fields
        k_div_deform<<<divBlocks, 256>>>(ro, rn, fields, i & 1);
        k_image_t<<<dim3(3, 96, 3), 256>>>(img,
                                           (i == LSTEPS - 1) ? rdout : (float*)nullptr,
                                           (i + 1) & 1);
    }
}